// round 6
// baseline (speedup 1.0000x reference)
#include <cuda_runtime.h>

#define DIMC   1024
#define NHEADS 16
#define HDIM   64
#define BATCH  2
#define SEQ    2048
#define MTOT   (BATCH * SEQ)   // 4096

// Scratch (device globals: allocation-free rule)
__device__ float g_q[BATCH * NHEADS * SEQ * HDIM];  // [B,H,N,D]
__device__ float g_k[BATCH * NHEADS * SEQ * HDIM];
__device__ float g_v[BATCH * NHEADS * SEQ * HDIM];
__device__ float g_o[BATCH * SEQ * DIMC];           // [B,N,C]

// ---------------------------------------------------------------------------
// 128x128x8 NT SGEMM core: C[r][c] = sum_k A[r][k] * Bm[c][k]
// 256 threads, 8x8 microtile per thread, register prefetch of next K-tile.
// ---------------------------------------------------------------------------
__device__ __forceinline__ void gemm_core(
    const float* __restrict__ A, const float* __restrict__ Bm, int Kdim,
    int row0, int col0, int tid,
    float (&As)[8][128], float (&Bs)[8][128], float (&acc)[8][8])
{
    const int lr = tid >> 1;          // 0..127
    const int lk = (tid & 1) << 2;    // 0 or 4
    const int tx = tid & 15;
    const int ty = tid >> 4;

    const float* Ap = A  + (size_t)(row0 + lr) * Kdim + lk;
    const float* Bp = Bm + (size_t)(col0 + lr) * Kdim + lk;

    float4 aR = *(const float4*)Ap;
    float4 bR = *(const float4*)Bp;

    for (int kt = 0; kt < Kdim; kt += 8) {
        As[lk + 0][lr] = aR.x; As[lk + 1][lr] = aR.y;
        As[lk + 2][lr] = aR.z; As[lk + 3][lr] = aR.w;
        Bs[lk + 0][lr] = bR.x; Bs[lk + 1][lr] = bR.y;
        Bs[lk + 2][lr] = bR.z; Bs[lk + 3][lr] = bR.w;
        __syncthreads();

        if (kt + 8 < Kdim) {           // prefetch next tile into registers
            aR = *(const float4*)(Ap + kt + 8);
            bR = *(const float4*)(Bp + kt + 8);
        }

        #pragma unroll
        for (int kk = 0; kk < 8; kk++) {
            float av[8], bv[8];
            *(float4*)&av[0] = *(const float4*)&As[kk][ty * 8];
            *(float4*)&av[4] = *(const float4*)&As[kk][ty * 8 + 4];
            *(float4*)&bv[0] = *(const float4*)&Bs[kk][tx * 8];
            *(float4*)&bv[4] = *(const float4*)&Bs[kk][tx * 8 + 4];
            #pragma unroll
            for (int i = 0; i < 8; i++)
                #pragma unroll
                for (int j = 0; j < 8; j++)
                    acc[i][j] += av[i] * bv[j];
        }
        __syncthreads();
    }
}

// ---------------------------------------------------------------------------
// QKV projection: y = x @ W.T, scattered to [B,H,N,D]. blockIdx.z picks W.
// ---------------------------------------------------------------------------
__global__ void __launch_bounds__(256) qkv_kernel(
    const float* __restrict__ x,
    const float* __restrict__ Wq,
    const float* __restrict__ Wk,
    const float* __restrict__ Wv)
{
    __shared__ float As[8][128];
    __shared__ float Bs[8][128];

    const int tid = threadIdx.x;
    const int z = blockIdx.z;
    const float* W = (z == 0) ? Wq : (z == 1) ? Wk : Wv;
    float* dst = (z == 0) ? g_q : (z == 1) ? g_k : g_v;

    const int row0 = blockIdx.y * 128;
    const int col0 = blockIdx.x * 128;

    float acc[8][8];
    #pragma unroll
    for (int i = 0; i < 8; i++)
        #pragma unroll
        for (int j = 0; j < 8; j++) acc[i][j] = 0.f;

    gemm_core(x, W, DIMC, row0, col0, tid, As, Bs, acc);

    const int tx = tid & 15;
    const int ty = tid >> 4;
    #pragma unroll
    for (int i = 0; i < 8; i++) {
        const int r = row0 + ty * 8 + i;
        const int b = r >> 11;         // /SEQ
        const int n = r & (SEQ - 1);
        #pragma unroll
        for (int jg = 0; jg < 2; jg++) {
            const int c = col0 + tx * 8 + jg * 4;
            const int h = c >> 6;      // /HDIM
            const int d = c & (HDIM - 1);
            float4 v = make_float4(acc[i][jg * 4 + 0], acc[i][jg * 4 + 1],
                                   acc[i][jg * 4 + 2], acc[i][jg * 4 + 3]);
            *(float4*)(dst + ((size_t)(b * NHEADS + h) * SEQ + n) * HDIM + d) = v;
        }
    }
}

// ---------------------------------------------------------------------------
// Flash attention: one block = 64 query rows of one (b,h).
// Shared: Qt (d-major, pre-scaled), KS (union of Kt and P), Vs. 48KB exactly.
// Softmax stats fully in registers via half-warp shuffles.
// ---------------------------------------------------------------------------
__global__ void __launch_bounds__(256) attn_kernel()
{
    __shared__ float Qt[64][64];   // Qt[d][i], scaled by 1/sqrt(D)
    __shared__ float KS[64][64];   // phase 1: Kt[d][j]; phase 2: P[i][j]
    __shared__ float Vs[64][64];   // V[j][d]

    const int tid = threadIdx.x;
    const int tx = tid & 15;       // cols
    const int ty = tid >> 4;       // rows
    const int bh = blockIdx.y;
    const int n0 = blockIdx.x * 64;

    const float* Qb = g_q + (size_t)bh * SEQ * HDIM;
    const float* Kb = g_k + (size_t)bh * SEQ * HDIM;
    const float* Vb = g_v + (size_t)bh * SEQ * HDIM;
    const float scale = 0.125f;    // 1/sqrt(64)

    // Load Q tile transposed (d-major), pre-scaled.
    {
        const int qn = tid & 63;
        const int d0 = (tid >> 6) * 4;
        #pragma unroll
        for (int it = 0; it < 4; it++) {
            const int d = d0 + it * 16;
            float4 v = *(const float4*)(Qb + (size_t)(n0 + qn) * HDIM + d);
            Qt[d + 0][qn] = v.x * scale;
            Qt[d + 1][qn] = v.y * scale;
            Qt[d + 2][qn] = v.z * scale;
            Qt[d + 3][qn] = v.w * scale;
        }
    }

    float mrow[4], lrow[4], o[4][4];
    #pragma unroll
    for (int r = 0; r < 4; r++) {
        mrow[r] = -1e30f;
        lrow[r] = 0.f;
        #pragma unroll
        for (int c = 0; c < 4; c++) o[r][c] = 0.f;
    }

    for (int t0 = 0; t0 < SEQ; t0 += 64) {
        __syncthreads();   // prior tile fully consumed (also orders Qt load, 1st iter)

        // Load K tile transposed: lanes span distinct j -> conflict-free stores.
        {
            const int kj = tid & 63;
            const int d0 = (tid >> 6) * 4;
            #pragma unroll
            for (int it = 0; it < 4; it++) {
                const int d = d0 + it * 16;
                float4 v = *(const float4*)(Kb + (size_t)(t0 + kj) * HDIM + d);
                KS[d + 0][kj] = v.x; KS[d + 1][kj] = v.y;
                KS[d + 2][kj] = v.z; KS[d + 3][kj] = v.w;
            }
        }
        // Load V tile linearly (fully coalesced).
        {
            const float4* src = (const float4*)(Vb + (size_t)t0 * HDIM);
            float4* dv = (float4*)&Vs[0][0];
            #pragma unroll
            for (int it = 0; it < 4; it++)
                dv[tid + it * 256] = src[tid + it * 256];
        }
        __syncthreads();

        // S = (Q*scale) @ K^T  (4x4 frag per thread)
        float s[4][4];
        #pragma unroll
        for (int r = 0; r < 4; r++)
            #pragma unroll
            for (int c = 0; c < 4; c++) s[r][c] = 0.f;

        #pragma unroll 8
        for (int d = 0; d < 64; d++) {
            float a[4], b[4];
            *(float4*)a = *(const float4*)&Qt[d][ty * 4];
            *(float4*)b = *(const float4*)&KS[d][tx * 4];
            #pragma unroll
            for (int r = 0; r < 4; r++)
                #pragma unroll
                for (int c = 0; c < 4; c++)
                    s[r][c] += a[r] * b[c];
        }

        // Online softmax; row stats replicated across the 16-lane half-warp.
        float corr[4];
        #pragma unroll
        for (int r = 0; r < 4; r++) {
            float mt = fmaxf(fmaxf(s[r][0], s[r][1]), fmaxf(s[r][2], s[r][3]));
            mt = fmaxf(mt, __shfl_xor_sync(0xffffffffu, mt, 1));
            mt = fmaxf(mt, __shfl_xor_sync(0xffffffffu, mt, 2));
            mt = fmaxf(mt, __shfl_xor_sync(0xffffffffu, mt, 4));
            mt = fmaxf(mt, __shfl_xor_sync(0xffffffffu, mt, 8));
            const float mnew = fmaxf(mrow[r], mt);
            const float c = __expf(mrow[r] - mnew);
            mrow[r] = mnew;
            float lt = 0.f;
            #pragma unroll
            for (int j = 0; j < 4; j++) {
                const float p = __expf(s[r][j] - mnew);
                s[r][j] = p;
                lt += p;
            }
            lt += __shfl_xor_sync(0xffffffffu, lt, 1);
            lt += __shfl_xor_sync(0xffffffffu, lt, 2);
            lt += __shfl_xor_sync(0xffffffffu, lt, 4);
            lt += __shfl_xor_sync(0xffffffffu, lt, 8);
            lrow[r] = lrow[r] * c + lt;
            corr[r] = c;
        }

        __syncthreads();   // everyone done reading Kt from KS

        // Write P into KS (union) and rescale O accumulators.
        #pragma unroll
        for (int r = 0; r < 4; r++) {
            *(float4*)&KS[ty * 4 + r][tx * 4] = *(float4*)&s[r][0];
            #pragma unroll
            for (int c = 0; c < 4; c++) o[r][c] *= corr[r];
        }
        __syncthreads();

        // O += P @ V
        #pragma unroll 8
        for (int j = 0; j < 64; j++) {
            float a[4], b[4];
            a[0] = KS[ty * 4 + 0][j];
            a[1] = KS[ty * 4 + 1][j];
            a[2] = KS[ty * 4 + 2][j];
            a[3] = KS[ty * 4 + 3][j];
            *(float4*)b = *(const float4*)&Vs[j][tx * 4];
            #pragma unroll
            for (int r = 0; r < 4; r++)
                #pragma unroll
                for (int c = 0; c < 4; c++)
                    o[r][c] += a[r] * b[c];
        }
    }

    // Normalize and write O directly in [B,N,C] layout.
    const int b = bh >> 4;
    const int h = bh & (NHEADS - 1);
    #pragma unroll
    for (int r = 0; r < 4; r++) {
        const float inv = 1.0f / lrow[r];
        const int n = n0 + ty * 4 + r;
        float4 v = make_float4(o[r][0] * inv, o[r][1] * inv,
                               o[r][2] * inv, o[r][3] * inv);
        *(float4*)(g_o + (size_t)(b * SEQ + n) * DIMC + h * HDIM + tx * 4) = v;
    }
}

// ---------------------------------------------------------------------------
// Output projection: out = O @ Wproj.T + bproj
// ---------------------------------------------------------------------------
__global__ void __launch_bounds__(256) proj_kernel(
    const float* __restrict__ Wp,
    const float* __restrict__ bias,
    float* __restrict__ out)
{
    __shared__ float As[8][128];
    __shared__ float Bs[8][128];

    const int tid = threadIdx.x;
    const int row0 = blockIdx.y * 128;
    const int col0 = blockIdx.x * 128;

    float acc[8][8];
    #pragma unroll
    for (int i = 0; i < 8; i++)
        #pragma unroll
        for (int j = 0; j < 8; j++) acc[i][j] = 0.f;

    gemm_core(g_o, Wp, DIMC, row0, col0, tid, As, Bs, acc);

    const int tx = tid & 15;
    const int ty = tid >> 4;
    #pragma unroll
    for (int i = 0; i < 8; i++) {
        const int r = row0 + ty * 8 + i;
        #pragma unroll
        for (int jg = 0; jg < 2; jg++) {
            const int c = col0 + tx * 8 + jg * 4;
            float4 bb = *(const float4*)(bias + c);
            float4 v = make_float4(acc[i][jg * 4 + 0] + bb.x,
                                   acc[i][jg * 4 + 1] + bb.y,
                                   acc[i][jg * 4 + 2] + bb.z,
                                   acc[i][jg * 4 + 3] + bb.w);
            *(float4*)(out + (size_t)r * DIMC + c) = v;
        }
    }
}

// ---------------------------------------------------------------------------
extern "C" void kernel_launch(void* const* d_in, const int* in_sizes, int n_in,
                              void* d_out, int out_size)
{
    const float* x     = (const float*)d_in[0];
    const float* Wq    = (const float*)d_in[1];
    const float* Wk    = (const float*)d_in[2];
    const float* Wv    = (const float*)d_in[3];
    const float* Wproj = (const float*)d_in[4];
    const float* bproj = (const float*)d_in[5];
    float* out = (float*)d_out;

    dim3 gQKV(DIMC / 128, MTOT / 128, 3);       // (8, 32, 3)
    qkv_kernel<<<gQKV, 256>>>(x, Wq, Wk, Wv);

    dim3 gAttn(SEQ / 64, BATCH * NHEADS);       // (32, 32)
    attn_kernel<<<gAttn, 256>>>();

    dim3 gProj(DIMC / 128, MTOT / 128);         // (8, 32)
    proj_kernel<<<gProj, 256>>>(Wproj, bproj, out);
}

// round 7
// speedup vs baseline: 1.0020x; 1.0020x over previous
#include <cuda_runtime.h>

#define DIMC   1024
#define NHEADS 16
#define HDIM   64
#define BATCH  2
#define SEQ    2048
#define MTOT   (BATCH * SEQ)   // 4096

// Scratch (device globals: allocation-free rule)
__device__ float g_q[BATCH * NHEADS * SEQ * HDIM];  // [B,H,N,D]
__device__ float g_k[BATCH * NHEADS * SEQ * HDIM];
__device__ float g_v[BATCH * NHEADS * SEQ * HDIM];
__device__ float g_o[BATCH * SEQ * DIMC];           // [B,N,C]

// ---------------------------------------------------------------------------
// 128x128x8 NT SGEMM core: C[r][c] = sum_k A[r][k] * Bm[c][k]
// 256 threads, 8x8 microtile per thread, register prefetch of next K-tile.
// ---------------------------------------------------------------------------
__device__ __forceinline__ void gemm_core(
    const float* __restrict__ A, const float* __restrict__ Bm, int Kdim,
    int row0, int col0, int tid,
    float (&As)[8][128], float (&Bs)[8][128], float (&acc)[8][8])
{
    const int lr = tid >> 1;          // 0..127
    const int lk = (tid & 1) << 2;    // 0 or 4
    const int tx = tid & 15;
    const int ty = tid >> 4;

    const float* Ap = A  + (size_t)(row0 + lr) * Kdim + lk;
    const float* Bp = Bm + (size_t)(col0 + lr) * Kdim + lk;

    float4 aR = *(const float4*)Ap;
    float4 bR = *(const float4*)Bp;

    for (int kt = 0; kt < Kdim; kt += 8) {
        As[lk + 0][lr] = aR.x; As[lk + 1][lr] = aR.y;
        As[lk + 2][lr] = aR.z; As[lk + 3][lr] = aR.w;
        Bs[lk + 0][lr] = bR.x; Bs[lk + 1][lr] = bR.y;
        Bs[lk + 2][lr] = bR.z; Bs[lk + 3][lr] = bR.w;
        __syncthreads();

        if (kt + 8 < Kdim) {           // prefetch next tile into registers
            aR = *(const float4*)(Ap + kt + 8);
            bR = *(const float4*)(Bp + kt + 8);
        }

        #pragma unroll
        for (int kk = 0; kk < 8; kk++) {
            float av[8], bv[8];
            *(float4*)&av[0] = *(const float4*)&As[kk][ty * 8];
            *(float4*)&av[4] = *(const float4*)&As[kk][ty * 8 + 4];
            *(float4*)&bv[0] = *(const float4*)&Bs[kk][tx * 8];
            *(float4*)&bv[4] = *(const float4*)&Bs[kk][tx * 8 + 4];
            #pragma unroll
            for (int i = 0; i < 8; i++)
                #pragma unroll
                for (int j = 0; j < 8; j++)
                    acc[i][j] += av[i] * bv[j];
        }
        __syncthreads();
    }
}

// ---------------------------------------------------------------------------
// QKV projection: y = x @ W.T, scattered to [B,H,N,D]. blockIdx.z picks W.
// ---------------------------------------------------------------------------
__global__ void __launch_bounds__(256) qkv_kernel(
    const float* __restrict__ x,
    const float* __restrict__ Wq,
    const float* __restrict__ Wk,
    const float* __restrict__ Wv)
{
    __shared__ float As[8][128];
    __shared__ float Bs[8][128];

    const int tid = threadIdx.x;
    const int z = blockIdx.z;
    const float* W = (z == 0) ? Wq : (z == 1) ? Wk : Wv;
    float* dst = (z == 0) ? g_q : (z == 1) ? g_k : g_v;

    const int row0 = blockIdx.y * 128;
    const int col0 = blockIdx.x * 128;

    float acc[8][8];
    #pragma unroll
    for (int i = 0; i < 8; i++)
        #pragma unroll
        for (int j = 0; j < 8; j++) acc[i][j] = 0.f;

    gemm_core(x, W, DIMC, row0, col0, tid, As, Bs, acc);

    const int tx = tid & 15;
    const int ty = tid >> 4;
    #pragma unroll
    for (int i = 0; i < 8; i++) {
        const int r = row0 + ty * 8 + i;
        const int b = r >> 11;         // /SEQ
        const int n = r & (SEQ - 1);
        #pragma unroll
        for (int jg = 0; jg < 2; jg++) {
            const int c = col0 + tx * 8 + jg * 4;
            const int h = c >> 6;      // /HDIM
            const int d = c & (HDIM - 1);
            float4 v = make_float4(acc[i][jg * 4 + 0], acc[i][jg * 4 + 1],
                                   acc[i][jg * 4 + 2], acc[i][jg * 4 + 3]);
            *(float4*)(dst + ((size_t)(b * NHEADS + h) * SEQ + n) * HDIM + d) = v;
        }
    }
}

// ---------------------------------------------------------------------------
// Flash attention: one block = 64 query rows of one (b,h).
// Shared: Qt (d-major, pre-scaled), KS (union of Kt and P), Vs. 48KB exactly.
// Softmax stats fully in registers via half-warp shuffles.
// ---------------------------------------------------------------------------
__global__ void __launch_bounds__(256) attn_kernel()
{
    __shared__ float Qt[64][64];   // Qt[d][i], scaled by 1/sqrt(D)
    __shared__ float KS[64][64];   // phase 1: Kt[d][j]; phase 2: P[i][j]
    __shared__ float Vs[64][64];   // V[j][d]

    const int tid = threadIdx.x;
    const int tx = tid & 15;       // cols
    const int ty = tid >> 4;       // rows
    const int bh = blockIdx.y;
    const int n0 = blockIdx.x * 64;

    const float* Qb = g_q + (size_t)bh * SEQ * HDIM;
    const float* Kb = g_k + (size_t)bh * SEQ * HDIM;
    const float* Vb = g_v + (size_t)bh * SEQ * HDIM;
    const float scale = 0.125f;    // 1/sqrt(64)

    // Load Q tile transposed (d-major), pre-scaled.
    {
        const int qn = tid & 63;
        const int d0 = (tid >> 6) * 4;
        #pragma unroll
        for (int it = 0; it < 4; it++) {
            const int d = d0 + it * 16;
            float4 v = *(const float4*)(Qb + (size_t)(n0 + qn) * HDIM + d);
            Qt[d + 0][qn] = v.x * scale;
            Qt[d + 1][qn] = v.y * scale;
            Qt[d + 2][qn] = v.z * scale;
            Qt[d + 3][qn] = v.w * scale;
        }
    }

    float mrow[4], lrow[4], o[4][4];
    #pragma unroll
    for (int r = 0; r < 4; r++) {
        mrow[r] = -1e30f;
        lrow[r] = 0.f;
        #pragma unroll
        for (int c = 0; c < 4; c++) o[r][c] = 0.f;
    }

    for (int t0 = 0; t0 < SEQ; t0 += 64) {
        __syncthreads();   // prior tile fully consumed (also orders Qt load, 1st iter)

        // Load K tile transposed: lanes span distinct j -> conflict-free stores.
        {
            const int kj = tid & 63;
            const int d0 = (tid >> 6) * 4;
            #pragma unroll
            for (int it = 0; it < 4; it++) {
                const int d = d0 + it * 16;
                float4 v = *(const float4*)(Kb + (size_t)(t0 + kj) * HDIM + d);
                KS[d + 0][kj] = v.x; KS[d + 1][kj] = v.y;
                KS[d + 2][kj] = v.z; KS[d + 3][kj] = v.w;
            }
        }
        // Load V tile linearly (fully coalesced).
        {
            const float4* src = (const float4*)(Vb + (size_t)t0 * HDIM);
            float4* dv = (float4*)&Vs[0][0];
            #pragma unroll
            for (int it = 0; it < 4; it++)
                dv[tid + it * 256] = src[tid + it * 256];
        }
        __syncthreads();

        // S = (Q*scale) @ K^T  (4x4 frag per thread)
        float s[4][4];
        #pragma unroll
        for (int r = 0; r < 4; r++)
            #pragma unroll
            for (int c = 0; c < 4; c++) s[r][c] = 0.f;

        #pragma unroll 8
        for (int d = 0; d < 64; d++) {
            float a[4], b[4];
            *(float4*)a = *(const float4*)&Qt[d][ty * 4];
            *(float4*)b = *(const float4*)&KS[d][tx * 4];
            #pragma unroll
            for (int r = 0; r < 4; r++)
                #pragma unroll
                for (int c = 0; c < 4; c++)
                    s[r][c] += a[r] * b[c];
        }

        // Online softmax; row stats replicated across the 16-lane half-warp.
        float corr[4];
        #pragma unroll
        for (int r = 0; r < 4; r++) {
            float mt = fmaxf(fmaxf(s[r][0], s[r][1]), fmaxf(s[r][2], s[r][3]));
            mt = fmaxf(mt, __shfl_xor_sync(0xffffffffu, mt, 1));
            mt = fmaxf(mt, __shfl_xor_sync(0xffffffffu, mt, 2));
            mt = fmaxf(mt, __shfl_xor_sync(0xffffffffu, mt, 4));
            mt = fmaxf(mt, __shfl_xor_sync(0xffffffffu, mt, 8));
            const float mnew = fmaxf(mrow[r], mt);
            const float c = __expf(mrow[r] - mnew);
            mrow[r] = mnew;
            float lt = 0.f;
            #pragma unroll
            for (int j = 0; j < 4; j++) {
                const float p = __expf(s[r][j] - mnew);
                s[r][j] = p;
                lt += p;
            }
            lt += __shfl_xor_sync(0xffffffffu, lt, 1);
            lt += __shfl_xor_sync(0xffffffffu, lt, 2);
            lt += __shfl_xor_sync(0xffffffffu, lt, 4);
            lt += __shfl_xor_sync(0xffffffffu, lt, 8);
            lrow[r] = lrow[r] * c + lt;
            corr[r] = c;
        }

        __syncthreads();   // everyone done reading Kt from KS

        // Write P into KS (union) and rescale O accumulators.
        #pragma unroll
        for (int r = 0; r < 4; r++) {
            *(float4*)&KS[ty * 4 + r][tx * 4] = *(float4*)&s[r][0];
            #pragma unroll
            for (int c = 0; c < 4; c++) o[r][c] *= corr[r];
        }
        __syncthreads();

        // O += P @ V
        #pragma unroll 8
        for (int j = 0; j < 64; j++) {
            float a[4], b[4];
            a[0] = KS[ty * 4 + 0][j];
            a[1] = KS[ty * 4 + 1][j];
            a[2] = KS[ty * 4 + 2][j];
            a[3] = KS[ty * 4 + 3][j];
            *(float4*)b = *(const float4*)&Vs[j][tx * 4];
            #pragma unroll
            for (int r = 0; r < 4; r++)
                #pragma unroll
                for (int c = 0; c < 4; c++)
                    o[r][c] += a[r] * b[c];
        }
    }

    // Normalize and write O directly in [B,N,C] layout.
    const int b = bh >> 4;
    const int h = bh & (NHEADS - 1);
    #pragma unroll
    for (int r = 0; r < 4; r++) {
        const float inv = 1.0f / lrow[r];
        const int n = n0 + ty * 4 + r;
        float4 v = make_float4(o[r][0] * inv, o[r][1] * inv,
                               o[r][2] * inv, o[r][3] * inv);
        *(float4*)(g_o + (size_t)(b * SEQ + n) * DIMC + h * HDIM + tx * 4) = v;
    }
}

// ---------------------------------------------------------------------------
// Output projection: out = O @ Wproj.T + bproj
// ---------------------------------------------------------------------------
__global__ void __launch_bounds__(256) proj_kernel(
    const float* __restrict__ Wp,
    const float* __restrict__ bias,
    float* __restrict__ out)
{
    __shared__ float As[8][128];
    __shared__ float Bs[8][128];

    const int tid = threadIdx.x;
    const int row0 = blockIdx.y * 128;
    const int col0 = blockIdx.x * 128;

    float acc[8][8];
    #pragma unroll
    for (int i = 0; i < 8; i++)
        #pragma unroll
        for (int j = 0; j < 8; j++) acc[i][j] = 0.f;

    gemm_core(g_o, Wp, DIMC, row0, col0, tid, As, Bs, acc);

    const int tx = tid & 15;
    const int ty = tid >> 4;
    #pragma unroll
    for (int i = 0; i < 8; i++) {
        const int r = row0 + ty * 8 + i;
        #pragma unroll
        for (int jg = 0; jg < 2; jg++) {
            const int c = col0 + tx * 8 + jg * 4;
            float4 bb = *(const float4*)(bias + c);
            float4 v = make_float4(acc[i][jg * 4 + 0] + bb.x,
                                   acc[i][jg * 4 + 1] + bb.y,
                                   acc[i][jg * 4 + 2] + bb.z,
                                   acc[i][jg * 4 + 3] + bb.w);
            *(float4*)(out + (size_t)r * DIMC + c) = v;
        }
    }
}

// ---------------------------------------------------------------------------
extern "C" void kernel_launch(void* const* d_in, const int* in_sizes, int n_in,
                              void* d_out, int out_size)
{
    const float* x     = (const float*)d_in[0];
    const float* Wq    = (const float*)d_in[1];
    const float* Wk    = (const float*)d_in[2];
    const float* Wv    = (const float*)d_in[3];
    const float* Wproj = (const float*)d_in[4];
    const float* bproj = (const float*)d_in[5];
    float* out = (float*)d_out;

    dim3 gQKV(DIMC / 128, MTOT / 128, 3);       // (8, 32, 3)
    qkv_kernel<<<gQKV, 256>>>(x, Wq, Wk, Wv);

    dim3 gAttn(SEQ / 64, BATCH * NHEADS);       // (32, 32)
    attn_kernel<<<gAttn, 256>>>();

    dim3 gProj(DIMC / 128, MTOT / 128);         // (8, 32)
    proj_kernel<<<gProj, 256>>>(Wproj, bproj, out);
}